// round 10
// baseline (speedup 1.0000x reference)
#include <cuda_runtime.h>

// H_13048110646034 v10 = v9 (persistent ticket warps, FFMA2, cp.async ring)
// with a SELF-RESETTING ticket: no init kernel, single graph node.
// Last-finisher warp restores g_ticket/g_done so every replay starts identical.

#define B_     8
#define N_     16384
#define P_     4096
#define NCTA   1332
#define NWARPS 2664

__device__ int g_ticket = NWARPS;
__device__ int g_done   = 0;

__device__ __forceinline__ void cp_async16(void* smem_dst, const void* gsrc) {
    unsigned saddr = (unsigned)__cvta_generic_to_shared(smem_dst);
    asm volatile("cp.async.cg.shared.global [%0], [%1], 16;\n" :: "r"(saddr), "l"(gsrc));
}
__device__ __forceinline__ void cp_commit() { asm volatile("cp.async.commit_group;\n"); }
template <int N>
__device__ __forceinline__ void cp_wait() {
    asm volatile("cp.async.wait_group %0;\n" :: "n"(N));
}
__device__ __forceinline__ void ffma2(unsigned long long& d,
                                      unsigned long long a,
                                      unsigned long long b) {
    asm("fma.rn.f32x2 %0, %1, %2, %0;" : "+l"(d) : "l"(a), "l"(b));
}
__device__ __forceinline__ unsigned long long dup2(float x) {
    unsigned long long r;
    unsigned u = __float_as_uint(x);
    asm("mov.b64 %0, {%1, %1};" : "=l"(r) : "r"(u));
    return r;
}

__global__ __launch_bounds__(64, 9)
void butterfly_local_v10(const float* __restrict__ x,
                         const float* __restrict__ Wrr,
                         const float* __restrict__ Wri,
                         const float* __restrict__ Wir,
                         const float* __restrict__ Wii,
                         const int*   __restrict__ perm,
                         float* __restrict__ out)
{
    const int w    = threadIdx.x >> 5;       // warp 0..1
    const int lane = threadIdx.x & 31;

    // Weights: [warp][buf][mat][i_local 4][o 64] = 16 KB (8 KB/warp ring)
    __shared__ float Wsm[2][2][4][4][64];
    // x: [warp][i 64][cb 16] = 8 KB
    __shared__ float xsm[2][64][16];

    const float* const Wm[4] = { Wrr, Wri, Wir, Wii };

    #define FILL_CHUNK(PP, CC, BUF)                                           \
        {                                                                     \
            const size_t _pq = (size_t)(PP) * 1024;                           \
            const int _c = (CC);                                              \
            _Pragma("unroll")                                                 \
            for (int k = 0; k < 8; k++) {                                     \
                const int mat = k >> 1;                                       \
                const int rem = (k & 1) * 32 + lane;                          \
                cp_async16(((float4*)&Wsm[w][BUF][mat][0][0]) + rem,          \
                           ((const float4*)Wm[mat]) + _pq + _c * 64 + rem);   \
            }                                                                 \
            cp_commit();                                                      \
        }

    #define GATHER_X(PP)                                                      \
        {                                                                     \
            const int _p = (PP);                                              \
            const int cb = lane & 15;                                         \
            const int hi = lane >> 4;                                         \
            _Pragma("unroll")                                                 \
            for (int it = 0; it < 8; it++) {                                  \
                const int jf = it * 2 + hi;                                   \
                const int j  = jf >> 2;                                       \
                const int f4 = jf & 3;                                        \
                const int n  = __ldg(&perm[_p * 4 + j]);                      \
                const float4 v = *(const float4*)&x[(((size_t)cb * N_) + n) * 16 + f4 * 4]; \
                const int i0 = j * 16 + f4 * 4;                               \
                xsm[w][i0 + 0][cb] = v.x;                                     \
                xsm[w][i0 + 1][cb] = v.y;                                     \
                xsm[w][i0 + 2][cb] = v.z;                                     \
                xsm[w][i0 + 3][cb] = v.w;                                     \
            }                                                                 \
        }

    int p = blockIdx.x * 2 + w;              // first p = global warp id (<2664)

    FILL_CHUNK(p, 0, 0);
    FILL_CHUNK(p, 1, 1);
    GATHER_X(p);
    __syncwarp();

    const int oslot = lane & 7;
    const int bslot = (lane >> 3) & 1;
    const int cout  = lane >> 4;
    const int matA  = cout * 2;
    const int matB  = cout * 2 + 1;

    while (p < P_) {
        unsigned long long aL0[4], aL1[4], aH0[4], aH1[4];
        #pragma unroll
        for (int k = 0; k < 4; k++) { aL0[k] = 0ull; aL1[k] = 0ull; aH0[k] = 0ull; aH1[k] = 0ull; }

        int p_next = P_;

        for (int c = 0; c < 16; c++) {
            cp_wait<1>();
            __syncwarp();
            const int buf = c & 1;

            #pragma unroll
            for (int ii = 0; ii < 4; ii++) {
                const int i = c * 4 + ii;
                const float4 xa = *(const float4*)&xsm[w][i][bslot * 8];
                const float4 xb = *(const float4*)&xsm[w][i][bslot * 8 + 4];

                const unsigned long long xr[4] = { dup2(xa.x), dup2(xa.z), dup2(xb.x), dup2(xb.z) };
                const unsigned long long xi[4] = { dup2(xa.y), dup2(xa.w), dup2(xb.y), dup2(xb.w) };

                const ulonglong2 wA0 = *(const ulonglong2*)&Wsm[w][buf][matA][ii][oslot * 4];
                const ulonglong2 wA1 = *(const ulonglong2*)&Wsm[w][buf][matA][ii][32 + oslot * 4];
                const ulonglong2 wB0 = *(const ulonglong2*)&Wsm[w][buf][matB][ii][oslot * 4];
                const ulonglong2 wB1 = *(const ulonglong2*)&Wsm[w][buf][matB][ii][32 + oslot * 4];

                #pragma unroll
                for (int k = 0; k < 4; k++) {
                    ffma2(aL0[k], xr[k], wA0.x); ffma2(aL1[k], xr[k], wA0.y);
                    ffma2(aL0[k], xi[k], wB0.x); ffma2(aL1[k], xi[k], wB0.y);
                    ffma2(aH0[k], xr[k], wA1.x); ffma2(aH1[k], xr[k], wA1.y);
                    ffma2(aH0[k], xi[k], wB1.x); ffma2(aH1[k], xi[k], wB1.y);
                }
            }

            __syncwarp();                    // all lanes done reading buf

            if (c == 11) {                   // grab next ticket mid-pipeline
                int t = 0;
                if (lane == 0) t = atomicAdd(&g_ticket, 1);
                p_next = __shfl_sync(0xffffffffu, t, 0);
            }

            const int slot = c + 2;
            if (slot < 16) {
                FILL_CHUNK(p, slot, slot & 1);
            } else if (p_next < P_) {        // seam prefetch of next p
                FILL_CHUNK(p_next, slot - 16, slot & 1);
            } else {
                cp_commit();                 // keep group accounting uniform
            }
        }

        // store: out[b, cout, 4p..4p+3, :] contiguous 64-float run
        #pragma unroll
        for (int k = 0; k < 4; k++) {
            const int b = bslot * 4 + k;
            const size_t off = (((size_t)(b * 2 + cout) * N_) + 4 * (size_t)p) * 16;
            ulonglong2 lo; lo.x = aL0[k]; lo.y = aL1[k];
            ulonglong2 hi; hi.x = aH0[k]; hi.y = aH1[k];
            *(ulonglong2*)&out[off + oslot * 4]      = lo;
            *(ulonglong2*)&out[off + 32 + oslot * 4] = hi;
        }

        if (p_next < P_) {                   // xsm free: all reads done
            GATHER_X(p_next);
            __syncwarp();
        }
        p = p_next;
    }

    cp_wait<0>();                            // drain dangling groups before exit

    // ---- self-reset for the next graph replay (single-kernel graph) ----
    // Every warp's final g_ticket atomicAdd precedes this fence; the last
    // warp to arrive restores the statics to their initial values.
    if (lane == 0) {
        __threadfence();
        const int d = atomicAdd(&g_done, 1);
        if (d == NWARPS - 1) {
            atomicExch(&g_ticket, NWARPS);
            atomicExch(&g_done, 0);
        }
    }
    #undef FILL_CHUNK
    #undef GATHER_X
}

extern "C" void kernel_launch(void* const* d_in, const int* in_sizes, int n_in,
                              void* d_out, int out_size)
{
    const float* x    = (const float*)d_in[0];
    const float* Wrr  = (const float*)d_in[1];
    const float* Wri  = (const float*)d_in[2];
    const float* Wir  = (const float*)d_in[3];
    const float* Wii  = (const float*)d_in[4];
    const int*   perm = (const int*)d_in[5];
    float* out = (float*)d_out;

    butterfly_local_v10<<<NCTA, 64>>>(x, Wrr, Wri, Wir, Wii, perm, out);
}

// round 11
// speedup vs baseline: 1.1059x; 1.1059x over previous
#include <cuda_runtime.h>

// H_13048110646034 v11 = v8 + 4-deep cp.async ring.
// One warp per p; ring = 4 bufs x (4 mats x 4 i-rows x 64) = 16 KB/warp.
// wait_group<2> keeps 3 groups (12 KB) in flight per warp -> prefetch
// distance ~3 chunk-computes, hiding loaded DRAM latency that the 2-deep
// ring exposed. Occupancy drops to 5 CTAs/SM (10 warps) - proven harmless
// (v7: 36 warps gave identical BW to 18).

#define B_  8
#define N_  16384
#define P_  4096

__device__ __forceinline__ void cp_async16(void* smem_dst, const void* gsrc) {
    unsigned saddr = (unsigned)__cvta_generic_to_shared(smem_dst);
    asm volatile("cp.async.cg.shared.global [%0], [%1], 16;\n" :: "r"(saddr), "l"(gsrc));
}
__device__ __forceinline__ void cp_commit() { asm volatile("cp.async.commit_group;\n"); }
template <int N>
__device__ __forceinline__ void cp_wait() {
    asm volatile("cp.async.wait_group %0;\n" :: "n"(N));
}
__device__ __forceinline__ void ffma2(unsigned long long& d,
                                      unsigned long long a,
                                      unsigned long long b) {
    asm("fma.rn.f32x2 %0, %1, %2, %0;" : "+l"(d) : "l"(a), "l"(b));
}
__device__ __forceinline__ unsigned long long dup2(float x) {
    unsigned long long r;
    unsigned u = __float_as_uint(x);
    asm("mov.b64 %0, {%1, %1};" : "=l"(r) : "r"(u));
    return r;
}

__global__ __launch_bounds__(64, 5)
void butterfly_local_v11(const float* __restrict__ x,
                         const float* __restrict__ Wrr,
                         const float* __restrict__ Wri,
                         const float* __restrict__ Wir,
                         const float* __restrict__ Wii,
                         const int*   __restrict__ perm,
                         float* __restrict__ out)
{
    const int w    = threadIdx.x >> 5;       // warp 0..1, one p each
    const int lane = threadIdx.x & 31;
    const int p    = blockIdx.x * 2 + w;

    // Weights: [warp][buf 4][mat][i_local 4][o 64] = 32 KB (16 KB/warp ring)
    __shared__ float Wsm[2][4][4][4][64];
    // x: [warp][i 64][cb 16] = 8 KB
    __shared__ float xsm[2][64][16];

    const float* const Wm[4] = { Wrr, Wri, Wir, Wii };
    const size_t pq = (size_t)p * 1024;      // float4 units per mat per p

    #define FILL_CHUNK(CC, BUF)                                               \
        {                                                                     \
            const int _c = (CC);                                              \
            _Pragma("unroll")                                                 \
            for (int k = 0; k < 8; k++) {                                     \
                const int mat = k >> 1;                                       \
                const int rem = (k & 1) * 32 + lane;                          \
                cp_async16(((float4*)&Wsm[w][BUF][mat][0][0]) + rem,          \
                           ((const float4*)Wm[mat]) + pq + _c * 64 + rem);    \
            }                                                                 \
            cp_commit();                                                      \
        }

    // prologue: 3 chunks in flight
    FILL_CHUNK(0, 0);
    FILL_CHUNK(1, 1);
    FILL_CHUNK(2, 2);

    // ---- x gather (cb = lane&15 spreads STS banks) ----
    {
        const int cb = lane & 15;
        const int hi = lane >> 4;
        #pragma unroll
        for (int it = 0; it < 8; it++) {
            const int jf = it * 2 + hi;      // 0..15
            const int j  = jf >> 2;
            const int f4 = jf & 3;
            const int n  = __ldg(&perm[p * 4 + j]);
            const float4 v = *(const float4*)&x[(((size_t)cb * N_) + n) * 16 + f4 * 4];
            const int i0 = j * 16 + f4 * 4;
            xsm[w][i0 + 0][cb] = v.x;
            xsm[w][i0 + 1][cb] = v.y;
            xsm[w][i0 + 2][cb] = v.z;
            xsm[w][i0 + 3][cb] = v.w;
        }
    }
    __syncwarp();

    const int oslot = lane & 7;              // o-quads oslot and oslot+8
    const int bslot = (lane >> 3) & 1;       // b = bslot*4 + 0..3
    const int cout  = lane >> 4;             // 0 = re, 1 = im
    const int matA  = cout * 2;
    const int matB  = cout * 2 + 1;

    unsigned long long aL0[4], aL1[4], aH0[4], aH1[4];
    #pragma unroll
    for (int k = 0; k < 4; k++) { aL0[k] = 0ull; aL1[k] = 0ull; aH0[k] = 0ull; aH1[k] = 0ull; }

    for (int c = 0; c < 16; c++) {
        cp_wait<2>();                        // chunk c landed (<=2 groups pending)
        __syncwarp();

        // issue fill for c+3 BEFORE compute: earliest possible issue point.
        // Overwrites buf (c-1)&3, whose readers all passed the previous
        // iteration's trailing __syncwarp.
        const int slot = c + 3;
        if (slot < 16) {
            FILL_CHUNK(slot, slot & 3);
        } else {
            cp_commit();                     // keep group accounting uniform
        }

        const int buf = c & 3;
        #pragma unroll
        for (int ii = 0; ii < 4; ii++) {
            const int i = c * 4 + ii;
            const float4 xa = *(const float4*)&xsm[w][i][bslot * 8];
            const float4 xb = *(const float4*)&xsm[w][i][bslot * 8 + 4];

            const unsigned long long xr[4] = { dup2(xa.x), dup2(xa.z), dup2(xb.x), dup2(xb.z) };
            const unsigned long long xi[4] = { dup2(xa.y), dup2(xa.w), dup2(xb.y), dup2(xb.w) };

            const ulonglong2 wA0 = *(const ulonglong2*)&Wsm[w][buf][matA][ii][oslot * 4];
            const ulonglong2 wA1 = *(const ulonglong2*)&Wsm[w][buf][matA][ii][32 + oslot * 4];
            const ulonglong2 wB0 = *(const ulonglong2*)&Wsm[w][buf][matB][ii][oslot * 4];
            const ulonglong2 wB1 = *(const ulonglong2*)&Wsm[w][buf][matB][ii][32 + oslot * 4];

            #pragma unroll
            for (int k = 0; k < 4; k++) {
                ffma2(aL0[k], xr[k], wA0.x); ffma2(aL1[k], xr[k], wA0.y);
                ffma2(aL0[k], xi[k], wB0.x); ffma2(aL1[k], xi[k], wB0.y);
                ffma2(aH0[k], xr[k], wA1.x); ffma2(aH1[k], xr[k], wA1.y);
                ffma2(aH0[k], xi[k], wB1.x); ffma2(aH1[k], xi[k], wB1.y);
            }
        }

        __syncwarp();                        // all lanes done reading buf
    }

    // ---- store: out[b, cout, 4p..4p+3, :] contiguous 64-float run ----
    #pragma unroll
    for (int k = 0; k < 4; k++) {
        const int b = bslot * 4 + k;
        const size_t off = (((size_t)(b * 2 + cout) * N_) + 4 * (size_t)p) * 16;
        ulonglong2 lo; lo.x = aL0[k]; lo.y = aL1[k];
        ulonglong2 hi; hi.x = aH0[k]; hi.y = aH1[k];
        *(ulonglong2*)&out[off + oslot * 4]      = lo;
        *(ulonglong2*)&out[off + 32 + oslot * 4] = hi;
    }
    #undef FILL_CHUNK
}

extern "C" void kernel_launch(void* const* d_in, const int* in_sizes, int n_in,
                              void* d_out, int out_size)
{
    const float* x    = (const float*)d_in[0];
    const float* Wrr  = (const float*)d_in[1];
    const float* Wri  = (const float*)d_in[2];
    const float* Wir  = (const float*)d_in[3];
    const float* Wii  = (const float*)d_in[4];
    const int*   perm = (const int*)d_in[5];
    float* out = (float*)d_out;

    butterfly_local_v11<<<P_ / 2, 64>>>(x, Wrr, Wri, Wir, Wii, perm, out);
}